// round 4
// baseline (speedup 1.0000x reference)
#include <cuda_runtime.h>
#include <cstddef>
#include <cstdint>

// ---------------- problem constants ----------------
#define KVOCAB 100000
#define KED    200
#define KH     100      // HW == HS == 100
#define KNC    10
#define KB     128
#define KS     40
#define KW     50
#define KSENT  (KB * KS)          // 5120

// ---------------- scratch (__device__ globals; no allocations allowed) ----
__device__ float g_gates[(size_t)KVOCAB * 600];   // 240 MB, reused as U buffer & sentence gates
__device__ float g_wenc[(size_t)KVOCAB * 200];    // 80 MB: per-vocab word encoding table
__device__ float g_scorew[KVOCAB];                // per-vocab word attention score
__device__ float g_svec[KSENT * 200];
__device__ float g_senc[KSENT * 200];
__device__ float g_scores[KSENT];
__device__ float g_dvec[KB * 200];
__device__ float g_WcatW[600 * KED];              // [w_Wih_f ; w_Wih_b]
__device__ float g_bihW[600];
__device__ float g_WcatS[600 * 200];              // [s_Wih_f ; s_Wih_b]
__device__ float g_bihS[600];

// ---------------- f32x2 helpers (FFMA2: ptxas never emits this from C++) ---
__device__ __forceinline__ unsigned long long pack2(float lo, float hi) {
    unsigned long long r;
    asm("mov.b64 %0, {%1, %2};" : "=l"(r) : "f"(lo), "f"(hi));
    return r;
}
__device__ __forceinline__ void unpack2(unsigned long long v, float& lo, float& hi) {
    asm("mov.b64 {%0, %1}, %2;" : "=f"(lo), "=f"(hi) : "l"(v));
}
__device__ __forceinline__ void ffma2(unsigned long long& d, unsigned long long a, unsigned long long b) {
    asm("fma.rn.f32x2 %0, %1, %2, %0;" : "+l"(d) : "l"(a), "l"(b));
}
__device__ __forceinline__ float fast_tanh(float x) {
    float y; asm("tanh.approx.f32 %0, %1;" : "=f"(y) : "f"(x)); return y;
}
__device__ __forceinline__ float sigmf(float x) {
    return 0.5f * fast_tanh(0.5f * x) + 0.5f;
}

// ---------------- SGEMM (NT): C[M,N] = A[M,K] * B[N,K]^T + bias[n] --------
// A row-major lda=K, B row-major ldb=K (both K-contiguous), C row-major ldc.
// Requires K % 8 == 0 (K is always 200 here). 128x128x8 tile, double-buffered,
// 256 threads, 8x8 per-thread tile, inner product in packed f32x2 FMAs.
__global__ __launch_bounds__(256)
void sgemm_nt(const float* __restrict__ A, const float* __restrict__ Bm,
              const float* __restrict__ bias, float* __restrict__ C,
              int M, int N, int K, int ldc)
{
    const int BM = 128, BN = 128, BK = 8, TM = 8, TN = 8;
    __shared__ float As[2][BK][BM];
    __shared__ float Bs[2][BK][BN];

    const int tid   = threadIdx.x;
    const int mBase = blockIdx.y * BM;
    const int nBase = blockIdx.x * BN;
    const int lrow  = tid >> 1;          // 0..127
    const int lcol  = (tid & 1) << 2;    // 0 or 4
    const int tx    = tid & 15;
    const int ty    = tid >> 4;
    const int tm0   = ty * TM;
    const int tn0   = tx * TN;

    unsigned long long acc[TM / 2][TN];
#pragma unroll
    for (int i = 0; i < TM / 2; i++)
#pragma unroll
        for (int j = 0; j < TN; j++) acc[i][j] = 0ull;

    const int nk = K >> 3;

    // prologue: stage tile 0
    {
        float4 va = make_float4(0.f, 0.f, 0.f, 0.f);
        float4 vb = make_float4(0.f, 0.f, 0.f, 0.f);
        int m = mBase + lrow;
        if (m < M) va = *reinterpret_cast<const float4*>(A + (size_t)m * K + lcol);
        int n = nBase + lrow;
        if (n < N) vb = *reinterpret_cast<const float4*>(Bm + (size_t)n * K + lcol);
        As[0][lcol + 0][lrow] = va.x; As[0][lcol + 1][lrow] = va.y;
        As[0][lcol + 2][lrow] = va.z; As[0][lcol + 3][lrow] = va.w;
        Bs[0][lcol + 0][lrow] = vb.x; Bs[0][lcol + 1][lrow] = vb.y;
        Bs[0][lcol + 2][lrow] = vb.z; Bs[0][lcol + 3][lrow] = vb.w;
    }
    __syncthreads();

    for (int kt = 0; kt < nk; kt++) {
        const int cur = kt & 1;
        float4 va = make_float4(0.f, 0.f, 0.f, 0.f);
        float4 vb = make_float4(0.f, 0.f, 0.f, 0.f);
        const bool hasNext = (kt + 1 < nk);
        if (hasNext) {
            int k = (kt + 1) * BK + lcol;
            int m = mBase + lrow;
            if (m < M) va = *reinterpret_cast<const float4*>(A + (size_t)m * K + k);
            int n = nBase + lrow;
            if (n < N) vb = *reinterpret_cast<const float4*>(Bm + (size_t)n * K + k);
        }
#pragma unroll
        for (int kk = 0; kk < BK; kk++) {
            float af[TM], bf[TN];
#pragma unroll
            for (int i = 0; i < TM; i++) af[i] = As[cur][kk][tm0 + i];
#pragma unroll
            for (int j = 0; j < TN; j++) bf[j] = Bs[cur][kk][tn0 + j];
            unsigned long long a2[TM / 2], b2[TN];
#pragma unroll
            for (int i = 0; i < TM / 2; i++) a2[i] = pack2(af[2 * i], af[2 * i + 1]);
#pragma unroll
            for (int j = 0; j < TN; j++) b2[j] = pack2(bf[j], bf[j]);
#pragma unroll
            for (int i = 0; i < TM / 2; i++)
#pragma unroll
                for (int j = 0; j < TN; j++) ffma2(acc[i][j], a2[i], b2[j]);
        }
        if (hasNext) {
            const int nxt = cur ^ 1;
            As[nxt][lcol + 0][lrow] = va.x; As[nxt][lcol + 1][lrow] = va.y;
            As[nxt][lcol + 2][lrow] = va.z; As[nxt][lcol + 3][lrow] = va.w;
            Bs[nxt][lcol + 0][lrow] = vb.x; Bs[nxt][lcol + 1][lrow] = vb.y;
            Bs[nxt][lcol + 2][lrow] = vb.z; Bs[nxt][lcol + 3][lrow] = vb.w;
            __syncthreads();
        }
    }

    // epilogue: unpack pairs (rows tm0+2i, tm0+2i+1), add bias, guarded store
#pragma unroll
    for (int i = 0; i < TM / 2; i++) {
#pragma unroll
        for (int j = 0; j < TN; j++) {
            float lo, hi;
            unpack2(acc[i][j], lo, hi);
            int n = nBase + tn0 + j;
            if (n < N) {
                float bv = bias[n];
                int m0 = mBase + tm0 + 2 * i;
                if (m0 < M)     C[(size_t)m0 * ldc + n]       = lo + bv;
                if (m0 + 1 < M) C[(size_t)(m0 + 1) * ldc + n] = hi + bv;
            }
        }
    }
}

// ---------------- GRU-from-zero pointwise -------------------------------
// gates layout per row (ldc=600): [r_f z_f n_f | r_b z_b n_b] (100 each),
// bih already added by the GEMM. h[m] = concat(h_f, h_b) (200).
__global__ void gru_pointwise(const float* __restrict__ g,
                              const float* __restrict__ bhh_f,
                              const float* __restrict__ bhh_b,
                              float* __restrict__ h, int M)
{
    int i = blockIdx.x * blockDim.x + threadIdx.x;
    if (i >= M * KH) return;
    int m = i / KH;
    int d = i - m * KH;
    const float* gr = g + (size_t)m * 600;
    float rf = sigmf(gr[d]       + bhh_f[d]);
    float zf = sigmf(gr[100 + d] + bhh_f[100 + d]);
    float nf = fast_tanh(gr[200 + d] + rf * bhh_f[200 + d]);
    float rb = sigmf(gr[300 + d] + bhh_b[d]);
    float zb = sigmf(gr[400 + d] + bhh_b[100 + d]);
    float nb = fast_tanh(gr[500 + d] + rb * bhh_b[200 + d]);
    float* hr = h + (size_t)m * 200;
    hr[d]       = (1.0f - zf) * nf;
    hr[100 + d] = (1.0f - zb) * nb;
}

// ---------------- score[m] = sum_d ctx[d] * tanh(U[m,d]) (U has bias) ----
__global__ void tanh_dot(const float* __restrict__ U, const float* __restrict__ ctx,
                         float* __restrict__ score, int M)
{
    int warp = (int)((blockIdx.x * blockDim.x + threadIdx.x) >> 5);
    int lane = threadIdx.x & 31;
    if (warp >= M) return;
    const float* u = U + (size_t)warp * 200;
    float s = 0.f;
    for (int d = lane; d < 200; d += 32) s += ctx[d] * fast_tanh(u[d]);
#pragma unroll
    for (int o = 16; o; o >>= 1) s += __shfl_xor_sync(0xffffffffu, s, o);
    if (lane == 0) score[warp] = s;
}

// ---------------- word attention combine: one block per sentence ---------
__global__ void word_attn(const int* __restrict__ x, const float* __restrict__ scoretab,
                          const float* __restrict__ wenc, float* __restrict__ svec)
{
    int s = blockIdx.x;                 // 0..KSENT-1
    __shared__ int   ids[KW];
    __shared__ float al[KW];
    __shared__ float sinv;
    int t = threadIdx.x;                // 256 threads
    if (t < KW) {
        int id = x[s * KW + t];
        ids[t] = id;
        al[t]  = scoretab[id];
    }
    __syncthreads();
    if (t == 0) {
        float mx = -1e30f;
        for (int w = 0; w < KW; w++) mx = fmaxf(mx, al[w]);
        float sum = 0.f;
        for (int w = 0; w < KW; w++) { float e = __expf(al[w] - mx); al[w] = e; sum += e; }
        sinv = 1.0f / sum;
    }
    __syncthreads();
    if (t < 200) {
        float acc = 0.f;
        float inv = sinv;
#pragma unroll 5
        for (int w = 0; w < KW; w++) acc += al[w] * wenc[(size_t)ids[w] * 200 + t];
        svec[(size_t)s * 200 + t] = acc * inv;
    }
}

// ---------------- sentence attention combine: one block per batch row ----
__global__ void sent_attn(const float* __restrict__ scoretab, const float* __restrict__ senc,
                          float* __restrict__ dvec)
{
    int b = blockIdx.x;
    __shared__ float al[KS];
    __shared__ float sinv;
    int t = threadIdx.x;
    if (t < KS) al[t] = scoretab[b * KS + t];
    __syncthreads();
    if (t == 0) {
        float mx = -1e30f;
        for (int i = 0; i < KS; i++) mx = fmaxf(mx, al[i]);
        float sum = 0.f;
        for (int i = 0; i < KS; i++) { float e = __expf(al[i] - mx); al[i] = e; sum += e; }
        sinv = 1.0f / sum;
    }
    __syncthreads();
    if (t < 200) {
        float acc = 0.f;
        float inv = sinv;
#pragma unroll 4
        for (int i = 0; i < KS; i++) acc += al[i] * senc[(size_t)(b * KS + i) * 200 + t];
        dvec[b * 200 + t] = acc * inv;
    }
}

// ---------------- classifier + log_softmax: one warp per batch row -------
__global__ void classifier(const float* __restrict__ dvec, const float* __restrict__ fcW,
                           const float* __restrict__ fcb, float* __restrict__ out)
{
    int b = blockIdx.x;
    int lane = threadIdx.x;             // 32 threads
    const float* dv = dvec + b * 200;
    float logit[KNC];
#pragma unroll
    for (int c = 0; c < KNC; c++) {
        float s = 0.f;
        for (int d = lane; d < 200; d += 32) s += dv[d] * fcW[c * 200 + d];
#pragma unroll
        for (int o = 16; o; o >>= 1) s += __shfl_xor_sync(0xffffffffu, s, o);
        logit[c] = s + fcb[c];          // xor-reduce -> all lanes hold the sum
    }
    if (lane == 0) {
        float mx = -1e30f;
        for (int c = 0; c < KNC; c++) mx = fmaxf(mx, logit[c]);
        float sum = 0.f;
        for (int c = 0; c < KNC; c++) sum += expf(logit[c] - mx);
        float lse = mx + logf(sum);
        for (int c = 0; c < KNC; c++) out[b * KNC + c] = logit[c] - lse;
    }
}

// ---------------- launch --------------------------------------------------
extern "C" void kernel_launch(void* const* d_in, const int* in_sizes, int n_in,
                              void* d_out, int out_size)
{
    (void)in_sizes; (void)n_in; (void)out_size;
    const int*   x     = (const int*)  d_in[0];
    const float* emb   = (const float*)d_in[1];
    const float* wWihf = (const float*)d_in[2];
    const float* wbihf = (const float*)d_in[3];
    const float* wbhhf = (const float*)d_in[4];
    const float* wWihb = (const float*)d_in[5];
    const float* wbihb = (const float*)d_in[6];
    const float* wbhhb = (const float*)d_in[7];
    const float* waW   = (const float*)d_in[8];
    const float* wab   = (const float*)d_in[9];
    const float* wactx = (const float*)d_in[10];
    const float* sWihf = (const float*)d_in[11];
    const float* sbihf = (const float*)d_in[12];
    const float* sbhhf = (const float*)d_in[13];
    const float* sWihb = (const float*)d_in[14];
    const float* sbihb = (const float*)d_in[15];
    const float* sbhhb = (const float*)d_in[16];
    const float* saW   = (const float*)d_in[17];
    const float* sab   = (const float*)d_in[18];
    const float* sactx = (const float*)d_in[19];
    const float* fcW   = (const float*)d_in[20];
    const float* fcb   = (const float*)d_in[21];
    float* out = (float*)d_out;

    float *gates, *wenc, *scorew, *svec, *senc, *scores, *dvec;
    float *WcatW, *bihW, *WcatS, *bihS;
    cudaGetSymbolAddress((void**)&gates,  g_gates);
    cudaGetSymbolAddress((void**)&wenc,   g_wenc);
    cudaGetSymbolAddress((void**)&scorew, g_scorew);
    cudaGetSymbolAddress((void**)&svec,   g_svec);
    cudaGetSymbolAddress((void**)&senc,   g_senc);
    cudaGetSymbolAddress((void**)&scores, g_scores);
    cudaGetSymbolAddress((void**)&dvec,   g_dvec);
    cudaGetSymbolAddress((void**)&WcatW,  g_WcatW);
    cudaGetSymbolAddress((void**)&bihW,   g_bihW);
    cudaGetSymbolAddress((void**)&WcatS,  g_WcatS);
    cudaGetSymbolAddress((void**)&bihS,   g_bihS);

    // concat fwd/bwd input weights & biases (capture-safe D2D copies)
    cudaMemcpyAsync(WcatW,            wWihf, (size_t)300 * KED * sizeof(float), cudaMemcpyDeviceToDevice, 0);
    cudaMemcpyAsync(WcatW + 300 * KED, wWihb, (size_t)300 * KED * sizeof(float), cudaMemcpyDeviceToDevice, 0);
    cudaMemcpyAsync(bihW,       wbihf, 300 * sizeof(float), cudaMemcpyDeviceToDevice, 0);
    cudaMemcpyAsync(bihW + 300, wbihb, 300 * sizeof(float), cudaMemcpyDeviceToDevice, 0);
    cudaMemcpyAsync(WcatS,            sWihf, (size_t)300 * 200 * sizeof(float), cudaMemcpyDeviceToDevice, 0);
    cudaMemcpyAsync(WcatS + 300 * 200, sWihb, (size_t)300 * 200 * sizeof(float), cudaMemcpyDeviceToDevice, 0);
    cudaMemcpyAsync(bihS,       sbihf, 300 * sizeof(float), cudaMemcpyDeviceToDevice, 0);
    cudaMemcpyAsync(bihS + 300, sbihb, 300 * sizeof(float), cudaMemcpyDeviceToDevice, 0);

    // --- word stage (per-vocab tables; tokens only gather) ---
    {   // gates = emb @ WcatW^T + bihW          [VOCAB, 600]
        dim3 grid((600 + 127) / 128, (KVOCAB + 127) / 128);
        sgemm_nt<<<grid, 256>>>(emb, WcatW, bihW, gates, KVOCAB, 600, KED, 600);
    }
    gru_pointwise<<<(KVOCAB * KH + 255) / 256, 256>>>(gates, wbhhf, wbhhb, wenc, KVOCAB);
    {   // U = wenc @ waW^T + wab (reuse gates buffer)   [VOCAB, 200]
        dim3 grid((200 + 127) / 128, (KVOCAB + 127) / 128);
        sgemm_nt<<<grid, 256>>>(wenc, waW, wab, gates, KVOCAB, 200, 200, 200);
    }
    tanh_dot<<<(KVOCAB + 7) / 8, 256>>>(gates, wactx, scorew, KVOCAB);
    word_attn<<<KSENT, 256>>>(x, scorew, wenc, svec);

    // --- sentence stage ---
    {   // gates_s = svec @ WcatS^T + bihS       [5120, 600]
        dim3 grid((600 + 127) / 128, (KSENT + 127) / 128);
        sgemm_nt<<<grid, 256>>>(svec, WcatS, bihS, gates, KSENT, 600, 200, 600);
    }
    gru_pointwise<<<(KSENT * KH + 255) / 256, 256>>>(gates, sbhhf, sbhhb, senc, KSENT);
    {   // U_s = senc @ saW^T + sab              [5120, 200]
        dim3 grid((200 + 127) / 128, (KSENT + 127) / 128);
        sgemm_nt<<<grid, 256>>>(senc, saW, sab, gates, KSENT, 200, 200, 200);
    }
    tanh_dot<<<(KSENT + 7) / 8, 256>>>(gates, sactx, scores, KSENT);
    sent_attn<<<KB, 256>>>(scores, senc, dvec);
    classifier<<<KB, 32>>>(dvec, fcW, fcb, out);
}